// round 4
// baseline (speedup 1.0000x reference)
#include <cuda_runtime.h>

// fastmax attention, b=4 h=16 n=1024 d=64, fp32 SIMT baseline.
// Decomposition:
//   prep:   Qn = q / ||q||, Kn = k / ||k||, Vp = v + 0.1*noise
//   qr:     QR[bh][i][m] = Qn_i . rpe2[m],  rpe2 = rpe_matrix[n-1:]   (causal: m <= i)
//   main:   S = 1 + Qn Kn^T + QR[i][i-j]  (masked to j<=i),  out = S Vp / rowsum(S)

#define B_  4
#define H_  16
#define N_  1024
#define D_  64
#define BH_ (B_*H_)

// Scratch (device globals: allocation-free per harness rules)
__device__ float g_qn[(size_t)BH_ * N_ * D_];           // 16 MB
__device__ float g_kn[(size_t)BH_ * N_ * D_];           // 16 MB
__device__ float g_vp[(size_t)BH_ * N_ * D_];           // 16 MB
__device__ float g_qr[(size_t)BH_ * N_ * N_];           // 256 MB

// ---------------------------------------------------------------------------
// prep: row-normalize q and k (one warp per 64-float row)
// ---------------------------------------------------------------------------
__global__ void prep_norm_kernel(const float* __restrict__ q,
                                 const float* __restrict__ k) {
    int gw   = (blockIdx.x * blockDim.x + threadIdx.x) >> 5;
    int lane = threadIdx.x & 31;
    const int total = BH_ * N_;
    const float* src;
    float* dst;
    int row;
    if (gw < total) { src = q; dst = g_qn; row = gw; }
    else            { src = k; dst = g_kn; row = gw - total; }
    const float2 v = reinterpret_cast<const float2*>(src + (size_t)row * D_)[lane];
    float ss = v.x * v.x + v.y * v.y;
    #pragma unroll
    for (int o = 16; o > 0; o >>= 1) ss += __shfl_xor_sync(0xffffffffu, ss, o);
    float inv = rsqrtf(ss);
    float2 r; r.x = v.x * inv; r.y = v.y * inv;
    reinterpret_cast<float2*>(dst + (size_t)row * D_)[lane] = r;
}

// ---------------------------------------------------------------------------
// prep: Vp = v + 0.1 * drop_noise (vectorized elementwise)
// ---------------------------------------------------------------------------
__global__ void prep_v_kernel(const float* __restrict__ v,
                              const float* __restrict__ nz) {
    int i = blockIdx.x * blockDim.x + threadIdx.x;
    float4 a = reinterpret_cast<const float4*>(v)[i];
    float4 b = reinterpret_cast<const float4*>(nz)[i];
    a.x = fmaf(0.1f, b.x, a.x);
    a.y = fmaf(0.1f, b.y, a.y);
    a.z = fmaf(0.1f, b.z, a.z);
    a.w = fmaf(0.1f, b.w, a.w);
    reinterpret_cast<float4*>(g_vp)[i] = a;
}

// ---------------------------------------------------------------------------
// QR[bh][i][m] = Qn[bh][i] . rpe2[m]   (64x64 tiles, lower-triangular tiles only)
// block = 256 threads = 16x16, each thread computes a 4x4 micro-tile
// ---------------------------------------------------------------------------
__global__ void __launch_bounds__(256) qr_kernel(const float* __restrict__ rpe) {
    if (blockIdx.x > blockIdx.y) return;   // m-tile must be <= i-tile
    const int m0 = blockIdx.x * 64;
    const int i0 = blockIdx.y * 64;
    const int bh = blockIdx.z;

    __shared__ float Qt[64 * 65];   // transposed: [kdim][row]
    __shared__ float Rt[64 * 65];   // transposed: [kdim][mrow]

    const int tid = threadIdx.x;
    const int tx = tid & 15, ty = tid >> 4;

    const float* qsrc = g_qn + ((size_t)bh * N_ + i0) * D_;
    const float* rsrc = rpe + (size_t)(N_ - 1 + m0) * D_;

    #pragma unroll
    for (int t = tid; t < 1024; t += 256) {
        int r = t >> 4, c = (t & 15) << 2;
        float4 x = *reinterpret_cast<const float4*>(qsrc + r * D_ + c);
        Qt[(c + 0) * 65 + r] = x.x; Qt[(c + 1) * 65 + r] = x.y;
        Qt[(c + 2) * 65 + r] = x.z; Qt[(c + 3) * 65 + r] = x.w;
        float4 y = *reinterpret_cast<const float4*>(rsrc + r * D_ + c);
        Rt[(c + 0) * 65 + r] = y.x; Rt[(c + 1) * 65 + r] = y.y;
        Rt[(c + 2) * 65 + r] = y.z; Rt[(c + 3) * 65 + r] = y.w;
    }
    __syncthreads();

    float acc[4][4] = {};
    #pragma unroll 8
    for (int kk = 0; kk < 64; kk++) {
        float a[4], b[4];
        #pragma unroll
        for (int u = 0; u < 4; u++) a[u] = Qt[kk * 65 + 4 * ty + u];
        #pragma unroll
        for (int w = 0; w < 4; w++) b[w] = Rt[kk * 65 + 4 * tx + w];
        #pragma unroll
        for (int u = 0; u < 4; u++)
            #pragma unroll
            for (int w = 0; w < 4; w++)
                acc[u][w] = fmaf(a[u], b[w], acc[u][w]);
    }

    float* dst = g_qr + (size_t)bh * N_ * N_;
    #pragma unroll
    for (int u = 0; u < 4; u++) {
        float4 o4 = make_float4(acc[u][0], acc[u][1], acc[u][2], acc[u][3]);
        *reinterpret_cast<float4*>(dst + (size_t)(i0 + 4 * ty + u) * N_ + m0 + 4 * tx) = o4;
    }
}

// ---------------------------------------------------------------------------
// Main fused attention: one block per (bh, i-tile). 64x64 tiles, causal loop
// over j-tiles. Two smem GEMMs per tile + bias gather from g_qr.
// ---------------------------------------------------------------------------
__global__ void __launch_bounds__(256) fastmax_main_kernel(float* __restrict__ out) {
    extern __shared__ float sm[];
    float* Qt = sm;             // [64][65] transposed (kdim-major)
    float* Kt = sm + 4160;      // [64][65] transposed
    float* Ss = sm + 8320;      // [64][65] row-major scores
    float* Vs = sm + 12480;     // [64][64] row-major
    __shared__ float dsum[64];

    const int it = 15 - blockIdx.x;   // heavy tiles launch first
    const int bh = blockIdx.y;
    const int i0 = it * 64;

    const int tid = threadIdx.x;
    const int tx = tid & 15, ty = tid >> 4;

    // Load Q tile (transposed)
    const float* qsrc = g_qn + ((size_t)bh * N_ + i0) * D_;
    #pragma unroll
    for (int t = tid; t < 1024; t += 256) {
        int r = t >> 4, c = (t & 15) << 2;
        float4 x = *reinterpret_cast<const float4*>(qsrc + r * D_ + c);
        Qt[(c + 0) * 65 + r] = x.x; Qt[(c + 1) * 65 + r] = x.y;
        Qt[(c + 2) * 65 + r] = x.z; Qt[(c + 3) * 65 + r] = x.w;
    }

    const float* qrp = g_qr + (size_t)bh * N_ * N_;

    float o[4][4] = {};
    float dp[4] = {};

    for (int jt = 0; jt <= it; jt++) {
        const int j0 = jt * 64;
        const float* ksrc = g_kn + ((size_t)bh * N_ + j0) * D_;
        const float* vsrc = g_vp + ((size_t)bh * N_ + j0) * D_;

        // Load K (transposed) + V tiles. Prior sync at loop end guards reuse.
        #pragma unroll
        for (int t = tid; t < 1024; t += 256) {
            int r = t >> 4, c = (t & 15) << 2;
            float4 x = *reinterpret_cast<const float4*>(ksrc + r * D_ + c);
            Kt[(c + 0) * 65 + r] = x.x; Kt[(c + 1) * 65 + r] = x.y;
            Kt[(c + 2) * 65 + r] = x.z; Kt[(c + 3) * 65 + r] = x.w;
            float4 y = *reinterpret_cast<const float4*>(vsrc + r * D_ + c);
            *reinterpret_cast<float4*>(&Vs[r * 64 + c]) = y;
        }

        // Prefetch bias values (hidden under GEMM1)
        float qrv[4][4];
        #pragma unroll
        for (int u = 0; u < 4; u++) {
            int gi = i0 + 4 * ty + u;
            #pragma unroll
            for (int w = 0; w < 4; w++) {
                int gj = j0 + 4 * tx + w;
                qrv[u][w] = (gj <= gi) ? __ldg(qrp + (size_t)gi * N_ + (gi - gj)) : 0.0f;
            }
        }
        __syncthreads();

        // GEMM1: s = Q . K^T
        float s[4][4] = {};
        #pragma unroll 8
        for (int kk = 0; kk < 64; kk++) {
            float a[4], b[4];
            #pragma unroll
            for (int u = 0; u < 4; u++) a[u] = Qt[kk * 65 + 4 * ty + u];
            #pragma unroll
            for (int w = 0; w < 4; w++) b[w] = Kt[kk * 65 + 4 * tx + w];
            #pragma unroll
            for (int u = 0; u < 4; u++)
                #pragma unroll
                for (int w = 0; w < 4; w++)
                    s[u][w] = fmaf(a[u], b[w], s[u][w]);
        }

        // epilogue: bias + 1 + causal mask, stage scores in smem, denom partials
        #pragma unroll
        for (int u = 0; u < 4; u++) {
            int gi = i0 + 4 * ty + u;
            #pragma unroll
            for (int w = 0; w < 4; w++) {
                int gj = j0 + 4 * tx + w;
                float val = (gj <= gi) ? (s[u][w] + 1.0f + qrv[u][w]) : 0.0f;
                Ss[(4 * ty + u) * 65 + 4 * tx + w] = val;
                dp[u] += val;
            }
        }
        __syncthreads();

        // GEMM2: o += S . V
        #pragma unroll 8
        for (int jj = 0; jj < 64; jj++) {
            float sa[4], vb[4];
            #pragma unroll
            for (int u = 0; u < 4; u++) sa[u] = Ss[(4 * ty + u) * 65 + jj];
            #pragma unroll
            for (int w = 0; w < 4; w++) vb[w] = Vs[jj * 64 + 4 * tx + w];
            #pragma unroll
            for (int u = 0; u < 4; u++)
                #pragma unroll
                for (int w = 0; w < 4; w++)
                    o[u][w] = fmaf(sa[u], vb[w], o[u][w]);
        }
        __syncthreads();
    }

    // denominator reduction across tx (reuse Ss)
    #pragma unroll
    for (int u = 0; u < 4; u++) Ss[tx * 64 + 4 * ty + u] = dp[u];
    __syncthreads();
    if (tid < 64) {
        float ssum = 0.0f;
        #pragma unroll
        for (int x = 0; x < 16; x++) ssum += Ss[x * 64 + tid];
        dsum[tid] = 1.0f / ssum;
    }
    __syncthreads();

    #pragma unroll
    for (int u = 0; u < 4; u++) {
        float r = dsum[4 * ty + u];
        float4 o4 = make_float4(o[u][0] * r, o[u][1] * r, o[u][2] * r, o[u][3] * r);
        *reinterpret_cast<float4*>(out + ((size_t)bh * N_ + i0 + 4 * ty + u) * D_ + 4 * tx) = o4;
    }
}

// ---------------------------------------------------------------------------
extern "C" void kernel_launch(void* const* d_in, const int* in_sizes, int n_in,
                              void* d_out, int out_size) {
    const float* q   = (const float*)d_in[0];
    const float* k   = (const float*)d_in[1];
    const float* v   = (const float*)d_in[2];
    const float* dn  = (const float*)d_in[3];
    const float* rpe = (const float*)d_in[4];
    float* out = (float*)d_out;

    // normalize q and k: 2*BH*N rows, 8 rows (warps) per 256-thread block
    prep_norm_kernel<<<(2 * BH_ * N_) / 8, 256>>>(q, k);
    // v + 0.1*noise: BH*N*D/4 float4 elements
    prep_v_kernel<<<(BH_ * N_ * D_ / 4) / 256, 256>>>(v, dn);
    // QR precompute
    qr_kernel<<<dim3(16, 16, BH_), 256>>>(rpe);
    // main fused attention
    const int smem_bytes = 16576 * sizeof(float);  // 66304 B
    cudaFuncSetAttribute(fastmax_main_kernel,
                         cudaFuncAttributeMaxDynamicSharedMemorySize, smem_bytes);
    fastmax_main_kernel<<<dim3(16, BH_), 256, smem_bytes>>>(out);
}

// round 6
// speedup vs baseline: 1.0368x; 1.0368x over previous
#include <cuda_runtime.h>
#include <cstdint>

// fastmax attention, b=4 h=16 n=1024 d=64.
// Round 5: 3xTF32 error-compensated mma.sync for all three GEMMs
// (x = x_hi + x_lo split; D += Ah*Bh + Ah*Bl + Al*Bh -> ~fp32 precision).
//   prep:   Qn = q/||q||, Kn = k/||k||, Vp = v + 0.1*noise   (full fp32)
//   qr:     QR[bh][i][m] = Qn_i . rpe2[m]
//   main:   S = 1 + Qn Kn^T + QR[i][i-j]  (j<=i),  out = S Vp / rowsum(S)

#define B_  4
#define H_  16
#define N_  1024
#define D_  64
#define BH_ (B_*H_)

__device__ float g_qn[(size_t)BH_ * N_ * D_];           // 16 MB fp32
__device__ float g_kn[(size_t)BH_ * N_ * D_];           // 16 MB fp32
__device__ float g_vp[(size_t)BH_ * N_ * D_];           // 16 MB fp32
__device__ float g_qr[(size_t)BH_ * N_ * N_];           // 256 MB fp32

// ---------------------------------------------------------------------------
// Split fp32 into tf32 hi + tf32 lo (captures ~22 mantissa bits total)
__device__ __forceinline__ void split2(float x, uint32_t& hi, uint32_t& lo) {
    asm("cvt.rna.tf32.f32 %0, %1;" : "=r"(hi) : "f"(x));
    float r = x - __uint_as_float(hi);
    asm("cvt.rna.tf32.f32 %0, %1;" : "=r"(lo) : "f"(r));
}

// D(16x8) += A(16x8,tf32) * B(8x8,tf32), fp32 accumulate
__device__ __forceinline__ void mma_tf32(float c[4], const uint32_t a[4],
                                         uint32_t b0, uint32_t b1) {
    asm("mma.sync.aligned.m16n8k8.row.col.f32.tf32.tf32.f32 "
        "{%0,%1,%2,%3}, {%4,%5,%6,%7}, {%8,%9}, {%0,%1,%2,%3};"
        : "+f"(c[0]), "+f"(c[1]), "+f"(c[2]), "+f"(c[3])
        : "r"(a[0]), "r"(a[1]), "r"(a[2]), "r"(a[3]), "r"(b0), "r"(b1));
}

// 3xTF32: full-precision fp32 operands a[4] (row frag), b0/b1 (col frag)
__device__ __forceinline__ void mma3(float c[4],
                                     const uint32_t ah[4], const uint32_t al[4],
                                     float b0f, float b1f) {
    uint32_t bh0, bl0, bh1, bl1;
    split2(b0f, bh0, bl0);
    split2(b1f, bh1, bl1);
    mma_tf32(c, ah, bh0, bh1);
    mma_tf32(c, ah, bl0, bl1);
    mma_tf32(c, al, bh0, bh1);
}

// ---------------------------------------------------------------------------
// prep: row-normalize q and k (one warp per 64-float row), full fp32
// ---------------------------------------------------------------------------
__global__ void prep_norm_kernel(const float* __restrict__ q,
                                 const float* __restrict__ k) {
    int gw   = (blockIdx.x * blockDim.x + threadIdx.x) >> 5;
    int lane = threadIdx.x & 31;
    const int total = BH_ * N_;
    const float* src;
    float* dst;
    int row;
    if (gw < total) { src = q; dst = g_qn; row = gw; }
    else            { src = k; dst = g_kn; row = gw - total; }
    const float2 v = reinterpret_cast<const float2*>(src + (size_t)row * D_)[lane];
    float ss = v.x * v.x + v.y * v.y;
    #pragma unroll
    for (int o = 16; o > 0; o >>= 1) ss += __shfl_xor_sync(0xffffffffu, ss, o);
    float inv = rsqrtf(ss);
    float2 r; r.x = v.x * inv; r.y = v.y * inv;
    reinterpret_cast<float2*>(dst + (size_t)row * D_)[lane] = r;
}

// ---------------------------------------------------------------------------
// prep: Vp = v + 0.1 * drop_noise, full fp32
// ---------------------------------------------------------------------------
__global__ void prep_v_kernel(const float* __restrict__ v,
                              const float* __restrict__ nz) {
    int i = blockIdx.x * blockDim.x + threadIdx.x;
    float4 a = reinterpret_cast<const float4*>(v)[i];
    float4 b = reinterpret_cast<const float4*>(nz)[i];
    a.x = fmaf(0.1f, b.x, a.x);
    a.y = fmaf(0.1f, b.y, a.y);
    a.z = fmaf(0.1f, b.z, a.z);
    a.w = fmaf(0.1f, b.w, a.w);
    reinterpret_cast<float4*>(g_vp)[i] = a;
}

// ---------------------------------------------------------------------------
// QR[bh][i][m] = Qn_i . rpe2[m], 128x64 tiles via 3xTF32 mma.
// block = 256 threads = 8 warps; warp w owns rows w*16..w*16+15.
// ---------------------------------------------------------------------------
__global__ void __launch_bounds__(256) qr_mma_kernel(const float* __restrict__ rpe) {
    const int mx = blockIdx.x, iy = blockIdx.y, bh = blockIdx.z;
    if (mx > 2 * iy + 1) return;

    extern __shared__ float sm[];
    float* Qs = sm;              // [128][68] fp32
    float* Rs = sm + 128 * 68;   // [64][68] fp32

    const int tid = threadIdx.x;
    const int w = tid >> 5, lane = tid & 31;
    const int g = lane >> 2, l = lane & 3;
    const int i0 = iy * 128, m0 = mx * 64;

    const float* qsrc = g_qn + ((size_t)bh * N_ + i0) * D_;
    #pragma unroll
    for (int e = tid; e < 2048; e += 256) {
        int r = e >> 4, c = (e & 15) << 2;
        *reinterpret_cast<float4*>(Qs + r * 68 + c) =
            *reinterpret_cast<const float4*>(qsrc + r * 64 + c);
    }
    const float* rsrc = rpe + (size_t)(N_ - 1 + m0) * D_;
    #pragma unroll
    for (int e = tid; e < 1024; e += 256) {
        int r = e >> 4, c = (e & 15) << 2;
        *reinterpret_cast<float4*>(Rs + r * 68 + c) =
            *reinterpret_cast<const float4*>(rsrc + r * 64 + c);
    }
    __syncthreads();

    const int r0 = w * 16 + g;
    float acc[8][4] = {};
    #pragma unroll
    for (int kk = 0; kk < 8; kk++) {
        uint32_t ah[4], al[4];
        split2(Qs[r0 * 68 + kk * 8 + l],           ah[0], al[0]);
        split2(Qs[(r0 + 8) * 68 + kk * 8 + l],     ah[1], al[1]);
        split2(Qs[r0 * 68 + kk * 8 + l + 4],       ah[2], al[2]);
        split2(Qs[(r0 + 8) * 68 + kk * 8 + l + 4], ah[3], al[3]);
        #pragma unroll
        for (int n = 0; n < 8; n++) {
            float b0 = Rs[(n * 8 + g) * 68 + kk * 8 + l];
            float b1 = Rs[(n * 8 + g) * 68 + kk * 8 + l + 4];
            mma3(acc[n], ah, al, b0, b1);
        }
    }

    float* dst = g_qr + (size_t)bh * N_ * N_;
    const int i_lo = i0 + r0, i_hi = i_lo + 8;
    #pragma unroll
    for (int n = 0; n < 8; n++) {
        int mc = m0 + n * 8 + 2 * l;
        *reinterpret_cast<float2*>(dst + (size_t)i_lo * N_ + mc) =
            make_float2(acc[n][0], acc[n][1]);
        *reinterpret_cast<float2*>(dst + (size_t)i_hi * N_ + mc) =
            make_float2(acc[n][2], acc[n][3]);
    }
}

// ---------------------------------------------------------------------------
// Main fused attention: block = (bh, 128-row i-tile), 8 warps.
// Warp w owns rows w*16..w*16+15; causal loop over 64-col j-tiles.
// Both GEMMs use 3xTF32; denominators accumulated from full-fp32 scores.
// ---------------------------------------------------------------------------
__global__ void __launch_bounds__(256) fastmax_mma_kernel(float* __restrict__ out) {
    extern __shared__ float sm[];
    float* Qs = sm;                      // [128][68], reused as Ss after Q extract
    float* Ks = sm + 128 * 68;           // [64][68]
    float* Vs = Ks + 64 * 68;            // [64][72]

    const int it = 7 - blockIdx.x;       // heavy tiles first
    const int bh = blockIdx.y;
    const int i0 = it * 128;

    const int tid = threadIdx.x;
    const int w = tid >> 5, lane = tid & 31;
    const int g = lane >> 2, l = lane & 3;
    const int r0 = w * 16 + g;

    // Load Q tile, extract per-warp A fragments (fp32) + pre-split hi/lo
    const float* qsrc = g_qn + ((size_t)bh * N_ + i0) * D_;
    #pragma unroll
    for (int e = tid; e < 2048; e += 256) {
        int r = e >> 4, c = (e & 15) << 2;
        *reinterpret_cast<float4*>(Qs + r * 68 + c) =
            *reinterpret_cast<const float4*>(qsrc + r * 64 + c);
    }
    __syncthreads();
    uint32_t qah[8][4], qal[8][4];
    #pragma unroll
    for (int kk = 0; kk < 8; kk++) {
        split2(Qs[r0 * 68 + kk * 8 + l],           qah[kk][0], qal[kk][0]);
        split2(Qs[(r0 + 8) * 68 + kk * 8 + l],     qah[kk][1], qal[kk][1]);
        split2(Qs[r0 * 68 + kk * 8 + l + 4],       qah[kk][2], qal[kk][2]);
        split2(Qs[(r0 + 8) * 68 + kk * 8 + l + 4], qah[kk][3], qal[kk][3]);
    }

    const int i_lo = i0 + r0, i_hi = i_lo + 8;
    const float* qlo = g_qr + (size_t)bh * N_ * N_ + (size_t)i_lo * (N_ + 1);
    const float* qhi = g_qr + (size_t)bh * N_ * N_ + (size_t)i_hi * (N_ + 1);

    float oacc[8][4] = {};
    float dp_lo = 0.0f, dp_hi = 0.0f;
    float* Ss = Qs;   // warp-private rows -> __syncwarp suffices for S staging

    const int njt = 2 * it + 2;
    for (int jt = 0; jt < njt; jt++) {
        const int j0 = jt * 64;
        const float* ksrc = g_kn + ((size_t)bh * N_ + j0) * D_;
        const float* vsrc = g_vp + ((size_t)bh * N_ + j0) * D_;
        #pragma unroll
        for (int e = tid; e < 1024; e += 256) {
            int r = e >> 4, c = (e & 15) << 2;
            *reinterpret_cast<float4*>(Ks + r * 68 + c) =
                *reinterpret_cast<const float4*>(ksrc + r * 64 + c);
            *reinterpret_cast<float4*>(Vs + r * 72 + c) =
                *reinterpret_cast<const float4*>(vsrc + r * 64 + c);
        }
        __syncthreads();

        // GEMM1: S = Q . K^T   (3xTF32)
        float sacc[8][4] = {};
        #pragma unroll
        for (int kk = 0; kk < 8; kk++)
            #pragma unroll
            for (int n = 0; n < 8; n++) {
                float b0 = Ks[(n * 8 + g) * 68 + kk * 8 + l];
                float b1 = Ks[(n * 8 + g) * 68 + kk * 8 + l + 4];
                mma3(sacc[n], qah[kk], qal[kk], b0, b1);
            }

        // Epilogue: +1, bias gather from g_qr, causal mask, denom partials,
        // stage full-fp32 S into warp-private smem rows.
        const bool full = (j0 + 63 <= i0);
        #pragma unroll
        for (int n = 0; n < 8; n++) {
            int jc = j0 + n * 8 + 2 * l;
            float v00 = sacc[n][0] + 1.0f;
            float v01 = sacc[n][1] + 1.0f;
            float v10 = sacc[n][2] + 1.0f;
            float v11 = sacc[n][3] + 1.0f;
            if (full) {
                v00 += __ldg(qlo - jc);     v01 += __ldg(qlo - (jc + 1));
                v10 += __ldg(qhi - jc);     v11 += __ldg(qhi - (jc + 1));
            } else {
                v00 = (jc     <= i_lo) ? v00 + __ldg(qlo - jc)       : 0.0f;
                v01 = (jc + 1 <= i_lo) ? v01 + __ldg(qlo - (jc + 1)) : 0.0f;
                v10 = (jc     <= i_hi) ? v10 + __ldg(qhi - jc)       : 0.0f;
                v11 = (jc + 1 <= i_hi) ? v11 + __ldg(qhi - (jc + 1)) : 0.0f;
            }
            dp_lo += v00 + v01;
            dp_hi += v10 + v11;
            *reinterpret_cast<float2*>(Ss + r0 * 68 + n * 8 + 2 * l) =
                make_float2(v00, v01);
            *reinterpret_cast<float2*>(Ss + (r0 + 8) * 68 + n * 8 + 2 * l) =
                make_float2(v10, v11);
        }
        __syncwarp();

        // GEMM2: O += S . V   (3xTF32; A = S strip split on load)
        #pragma unroll
        for (int kk = 0; kk < 8; kk++) {
            uint32_t ah[4], al[4];
            split2(Ss[r0 * 68 + kk * 8 + l],           ah[0], al[0]);
            split2(Ss[(r0 + 8) * 68 + kk * 8 + l],     ah[1], al[1]);
            split2(Ss[r0 * 68 + kk * 8 + l + 4],       ah[2], al[2]);
            split2(Ss[(r0 + 8) * 68 + kk * 8 + l + 4], ah[3], al[3]);
            #pragma unroll
            for (int n = 0; n < 8; n++) {
                float b0 = Vs[(kk * 8 + l) * 72 + n * 8 + g];
                float b1 = Vs[(kk * 8 + l + 4) * 72 + n * 8 + g];
                mma3(oacc[n], ah, al, b0, b1);
            }
        }
        __syncthreads();
    }

    // Row denominators: reduce partials across the 4 lanes of each quad.
    dp_lo += __shfl_xor_sync(0xffffffffu, dp_lo, 1);
    dp_lo += __shfl_xor_sync(0xffffffffu, dp_lo, 2);
    dp_hi += __shfl_xor_sync(0xffffffffu, dp_hi, 1);
    dp_hi += __shfl_xor_sync(0xffffffffu, dp_hi, 2);
    const float rlo = 1.0f / dp_lo;
    const float rhi = 1.0f / dp_hi;

    float* olo = out + ((size_t)bh * N_ + i_lo) * D_;
    float* ohi = out + ((size_t)bh * N_ + i_hi) * D_;
    #pragma unroll
    for (int n = 0; n < 8; n++) {
        int dc = n * 8 + 2 * l;
        *reinterpret_cast<float2*>(olo + dc) =
            make_float2(oacc[n][0] * rlo, oacc[n][1] * rlo);
        *reinterpret_cast<float2*>(ohi + dc) =
            make_float2(oacc[n][2] * rhi, oacc[n][3] * rhi);
    }
}

// ---------------------------------------------------------------------------
extern "C" void kernel_launch(void* const* d_in, const int* in_sizes, int n_in,
                              void* d_out, int out_size) {
    const float* q   = (const float*)d_in[0];
    const float* k   = (const float*)d_in[1];
    const float* v   = (const float*)d_in[2];
    const float* dn  = (const float*)d_in[3];
    const float* rpe = (const float*)d_in[4];
    float* out = (float*)d_out;

    prep_norm_kernel<<<(2 * BH_ * N_) / 8, 256>>>(q, k);
    prep_v_kernel<<<(BH_ * N_ * D_ / 4) / 256, 256>>>(v, dn);

    const int qr_smem = (128 * 68 + 64 * 68) * sizeof(float);       // 52224 B
    cudaFuncSetAttribute(qr_mma_kernel,
                         cudaFuncAttributeMaxDynamicSharedMemorySize, qr_smem);
    qr_mma_kernel<<<dim3(16, 8, BH_), 256, qr_smem>>>(rpe);

    const int mn_smem = (128 * 68 + 64 * 68 + 64 * 72) * sizeof(float);  // 70656 B
    cudaFuncSetAttribute(fastmax_mma_kernel,
                         cudaFuncAttributeMaxDynamicSharedMemorySize, mn_smem);
    fastmax_mma_kernel<<<dim3(8, BH_), 256, mn_smem>>>(out);
}

// round 7
// speedup vs baseline: 1.5598x; 1.5044x over previous
#include <cuda_runtime.h>
#include <cstdint>

// fastmax attention, b=4 h=16 n=1024 d=64.
// Round 6: 3xTF32 mma + pre-split hi/lo K,V in global + double-buffered
// cp.async tile pipeline + hoisted bias gather.
//   prep:   Qn = q/||q|| (fp32); K,V pre-split to tf32 hi/lo pairs
//   qr:     QR[bh][i][m] = Qn_i . rpe2[m]
//   main:   S = 1 + Qn Kn^T + QR[i][i-j]  (j<=i),  out = S Vp / rowsum(S)

#define B_  4
#define H_  16
#define N_  1024
#define D_  64
#define BH_ (B_*H_)

__device__ float g_qn [(size_t)BH_ * N_ * D_];          // fp32 normalized q
__device__ float g_knh[(size_t)BH_ * N_ * D_];          // tf32-hi of normalized k
__device__ float g_knl[(size_t)BH_ * N_ * D_];          // tf32-lo
__device__ float g_vph[(size_t)BH_ * N_ * D_];          // tf32-hi of v+0.1*noise
__device__ float g_vpl[(size_t)BH_ * N_ * D_];          // tf32-lo
__device__ float g_qr [(size_t)BH_ * N_ * N_];          // fp32 bias table

// ---------------------------------------------------------------------------
__device__ __forceinline__ void split2(float x, uint32_t& hi, uint32_t& lo) {
    asm("cvt.rna.tf32.f32 %0, %1;" : "=r"(hi) : "f"(x));
    float r = x - __uint_as_float(hi);
    asm("cvt.rna.tf32.f32 %0, %1;" : "=r"(lo) : "f"(r));
}

__device__ __forceinline__ void mma_tf32(float c[4], const uint32_t a[4],
                                         uint32_t b0, uint32_t b1) {
    asm("mma.sync.aligned.m16n8k8.row.col.f32.tf32.tf32.f32 "
        "{%0,%1,%2,%3}, {%4,%5,%6,%7}, {%8,%9}, {%0,%1,%2,%3};"
        : "+f"(c[0]), "+f"(c[1]), "+f"(c[2]), "+f"(c[3])
        : "r"(a[0]), "r"(a[1]), "r"(a[2]), "r"(a[3]), "r"(b0), "r"(b1));
}

// 3xTF32 with full-fp32 B split on load (used by qr kernel + GEMM2 A-splits)
__device__ __forceinline__ void mma3(float c[4],
                                     const uint32_t ah[4], const uint32_t al[4],
                                     float b0f, float b1f) {
    uint32_t bh0, bl0, bh1, bl1;
    split2(b0f, bh0, bl0);
    split2(b1f, bh1, bl1);
    mma_tf32(c, ah, bh0, bh1);
    mma_tf32(c, al, bh0, bh1);
    mma_tf32(c, ah, bl0, bl1);
}

__device__ __forceinline__ void cp_async16(void* sdst, const void* gsrc) {
    uint32_t s = (uint32_t)__cvta_generic_to_shared(sdst);
    asm volatile("cp.async.cg.shared.global [%0], [%1], 16;" :: "r"(s), "l"(gsrc));
}

// ---------------------------------------------------------------------------
// prep: normalize q -> g_qn (fp32); normalize k -> split tf32 hi/lo
// ---------------------------------------------------------------------------
__global__ void prep_norm_kernel(const float* __restrict__ q,
                                 const float* __restrict__ k) {
    int gw   = (blockIdx.x * blockDim.x + threadIdx.x) >> 5;
    int lane = threadIdx.x & 31;
    const int total = BH_ * N_;
    const bool is_q = (gw < total);
    const int row = is_q ? gw : gw - total;
    const float* src = is_q ? q : k;
    const float2 v = reinterpret_cast<const float2*>(src + (size_t)row * D_)[lane];
    float ss = v.x * v.x + v.y * v.y;
    #pragma unroll
    for (int o = 16; o > 0; o >>= 1) ss += __shfl_xor_sync(0xffffffffu, ss, o);
    float inv = rsqrtf(ss);
    float x = v.x * inv, y = v.y * inv;
    if (is_q) {
        reinterpret_cast<float2*>(g_qn + (size_t)row * D_)[lane] = make_float2(x, y);
    } else {
        uint32_t xh, xl, yh, yl;
        split2(x, xh, xl);
        split2(y, yh, yl);
        reinterpret_cast<float2*>(g_knh + (size_t)row * D_)[lane] =
            make_float2(__uint_as_float(xh), __uint_as_float(yh));
        reinterpret_cast<float2*>(g_knl + (size_t)row * D_)[lane] =
            make_float2(__uint_as_float(xl), __uint_as_float(yl));
    }
}

// ---------------------------------------------------------------------------
// prep: Vp = v + 0.1*noise -> split tf32 hi/lo
// ---------------------------------------------------------------------------
__global__ void prep_v_kernel(const float* __restrict__ v,
                              const float* __restrict__ nz) {
    int i = blockIdx.x * blockDim.x + threadIdx.x;
    float4 a = reinterpret_cast<const float4*>(v)[i];
    float4 b = reinterpret_cast<const float4*>(nz)[i];
    float4 h, l;
    uint32_t th, tl;
    split2(fmaf(0.1f, b.x, a.x), th, tl); h.x = __uint_as_float(th); l.x = __uint_as_float(tl);
    split2(fmaf(0.1f, b.y, a.y), th, tl); h.y = __uint_as_float(th); l.y = __uint_as_float(tl);
    split2(fmaf(0.1f, b.z, a.z), th, tl); h.z = __uint_as_float(th); l.z = __uint_as_float(tl);
    split2(fmaf(0.1f, b.w, a.w), th, tl); h.w = __uint_as_float(th); l.w = __uint_as_float(tl);
    reinterpret_cast<float4*>(g_vph)[i] = h;
    reinterpret_cast<float4*>(g_vpl)[i] = l;
}

// ---------------------------------------------------------------------------
// QR[bh][i][m] = Qn_i . rpe2[m], 128x64 tiles via 3xTF32 mma.
// ---------------------------------------------------------------------------
__global__ void __launch_bounds__(256) qr_mma_kernel(const float* __restrict__ rpe) {
    const int mx = blockIdx.x, iy = blockIdx.y, bh = blockIdx.z;
    if (mx > 2 * iy + 1) return;

    extern __shared__ float sm[];
    float* Qs = sm;              // [128][68]
    float* Rs = sm + 128 * 68;   // [64][68]

    const int tid = threadIdx.x;
    const int w = tid >> 5, lane = tid & 31;
    const int g = lane >> 2, l = lane & 3;
    const int i0 = iy * 128, m0 = mx * 64;

    const float* qsrc = g_qn + ((size_t)bh * N_ + i0) * D_;
    #pragma unroll
    for (int e = tid; e < 2048; e += 256) {
        int r = e >> 4, c = (e & 15) << 2;
        *reinterpret_cast<float4*>(Qs + r * 68 + c) =
            *reinterpret_cast<const float4*>(qsrc + r * 64 + c);
    }
    const float* rsrc = rpe + (size_t)(N_ - 1 + m0) * D_;
    #pragma unroll
    for (int e = tid; e < 1024; e += 256) {
        int r = e >> 4, c = (e & 15) << 2;
        *reinterpret_cast<float4*>(Rs + r * 68 + c) =
            *reinterpret_cast<const float4*>(rsrc + r * 64 + c);
    }
    __syncthreads();

    const int r0 = w * 16 + g;
    float acc[8][4] = {};
    #pragma unroll
    for (int kk = 0; kk < 8; kk++) {
        uint32_t ah[4], al[4];
        split2(Qs[r0 * 68 + kk * 8 + l],           ah[0], al[0]);
        split2(Qs[(r0 + 8) * 68 + kk * 8 + l],     ah[1], al[1]);
        split2(Qs[r0 * 68 + kk * 8 + l + 4],       ah[2], al[2]);
        split2(Qs[(r0 + 8) * 68 + kk * 8 + l + 4], ah[3], al[3]);
        #pragma unroll
        for (int n = 0; n < 8; n++) {
            float b0 = Rs[(n * 8 + g) * 68 + kk * 8 + l];
            float b1 = Rs[(n * 8 + g) * 68 + kk * 8 + l + 4];
            mma3(acc[n], ah, al, b0, b1);
        }
    }

    float* dst = g_qr + (size_t)bh * N_ * N_;
    const int i_lo = i0 + r0, i_hi = i_lo + 8;
    #pragma unroll
    for (int n = 0; n < 8; n++) {
        int mc = m0 + n * 8 + 2 * l;
        *reinterpret_cast<float2*>(dst + (size_t)i_lo * N_ + mc) =
            make_float2(acc[n][0], acc[n][1]);
        *reinterpret_cast<float2*>(dst + (size_t)i_hi * N_ + mc) =
            make_float2(acc[n][2], acc[n][3]);
    }
}

// ---------------------------------------------------------------------------
// Main fused attention: block = (bh, 128-row i-tile), 8 warps.
// Double-buffered cp.async K/V (pre-split hi/lo), hoisted bias gather.
// ---------------------------------------------------------------------------
__global__ void __launch_bounds__(256) fastmax_mma_kernel(float* __restrict__ out) {
    extern __shared__ float sm[];
    float* Qs  = sm;                 // [128][68], reused as Ss after Q extract
    float* Khs = sm + 8704;          // 2 x [64][68]
    float* Kls = Khs + 8704;         // 2 x [64][68]
    float* Vhs = Kls + 8704;         // 2 x [64][72]
    float* Vls = Vhs + 9216;         // 2 x [64][72]

    const int it = 7 - blockIdx.x;   // heavy tiles first
    const int bh = blockIdx.y;
    const int i0 = it * 128;

    const int tid = threadIdx.x;
    const int w = tid >> 5, lane = tid & 31;
    const int g = lane >> 2, l = lane & 3;
    const int r0 = w * 16 + g;

    auto load_tile_async = [&](int j0, int buf) {
        const size_t base = ((size_t)bh * N_ + j0) * D_;
        const float* kh = g_knh + base;
        const float* kl = g_knl + base;
        const float* vh = g_vph + base;
        const float* vl = g_vpl + base;
        float* Kh = Khs + buf * 4352;
        float* Kl = Kls + buf * 4352;
        float* Vh = Vhs + buf * 4608;
        float* Vl = Vls + buf * 4608;
        #pragma unroll
        for (int e = tid; e < 1024; e += 256) {
            int r = e >> 4, c = (e & 15) << 2;
            cp_async16(Kh + r * 68 + c, kh + r * 64 + c);
            cp_async16(Kl + r * 68 + c, kl + r * 64 + c);
            cp_async16(Vh + r * 72 + c, vh + r * 64 + c);
            cp_async16(Vl + r * 72 + c, vl + r * 64 + c);
        }
    };

    // Load Q tile, extract per-warp A fragments, pre-split hi/lo
    const float* qsrc = g_qn + ((size_t)bh * N_ + i0) * D_;
    #pragma unroll
    for (int e = tid; e < 2048; e += 256) {
        int r = e >> 4, c = (e & 15) << 2;
        *reinterpret_cast<float4*>(Qs + r * 68 + c) =
            *reinterpret_cast<const float4*>(qsrc + r * 64 + c);
    }
    // kick off K/V preload for tile 0 while Q settles
    load_tile_async(0, 0);
    asm volatile("cp.async.commit_group;");
    __syncthreads();

    uint32_t qah[8][4], qal[8][4];
    #pragma unroll
    for (int kk = 0; kk < 8; kk++) {
        split2(Qs[r0 * 68 + kk * 8 + l],           qah[kk][0], qal[kk][0]);
        split2(Qs[(r0 + 8) * 68 + kk * 8 + l],     qah[kk][1], qal[kk][1]);
        split2(Qs[r0 * 68 + kk * 8 + l + 4],       qah[kk][2], qal[kk][2]);
        split2(Qs[(r0 + 8) * 68 + kk * 8 + l + 4], qah[kk][3], qal[kk][3]);
    }

    const int i_lo = i0 + r0, i_hi = i_lo + 8;
    const float* qlo = g_qr + (size_t)bh * N_ * N_ + (size_t)i_lo * (N_ + 1);
    const float* qhi = g_qr + (size_t)bh * N_ * N_ + (size_t)i_hi * (N_ + 1);

    float oacc[8][4] = {};
    float dp_lo = 0.0f, dp_hi = 0.0f;
    float* Ss = Qs;   // warp-private rows

    asm volatile("cp.async.wait_group 0;");
    __syncthreads();

    const int njt = 2 * it + 2;
    for (int jt = 0; jt < njt; jt++) {
        const int j0 = jt * 64;
        const int cur = jt & 1;

        // issue next tile's copies (overlap with this tile's compute)
        if (jt + 1 < njt) load_tile_async((jt + 1) * 64, cur ^ 1);
        asm volatile("cp.async.commit_group;");

        // hoisted bias gather (completes under GEMM1)
        const bool full = (j0 + 63 <= i0);
        float qrv[8][4];
        #pragma unroll
        for (int n = 0; n < 8; n++) {
            int jc = j0 + n * 8 + 2 * l;
            if (full) {
                qrv[n][0] = __ldg(qlo - jc);
                qrv[n][1] = __ldg(qlo - (jc + 1));
                qrv[n][2] = __ldg(qhi - jc);
                qrv[n][3] = __ldg(qhi - (jc + 1));
            } else {
                qrv[n][0] = (jc     <= i_lo) ? __ldg(qlo - jc)       : 0.0f;
                qrv[n][1] = (jc + 1 <= i_lo) ? __ldg(qlo - (jc + 1)) : 0.0f;
                qrv[n][2] = (jc     <= i_hi) ? __ldg(qhi - jc)       : 0.0f;
                qrv[n][3] = (jc + 1 <= i_hi) ? __ldg(qhi - (jc + 1)) : 0.0f;
            }
        }

        const float* Kh = Khs + cur * 4352;
        const float* Kl = Kls + cur * 4352;
        const float* Vh = Vhs + cur * 4608;
        const float* Vl = Vls + cur * 4608;

        // GEMM1: S = Q . K^T  (3xTF32, K pre-split)
        float sacc[8][4] = {};
        #pragma unroll
        for (int kk = 0; kk < 8; kk++)
            #pragma unroll
            for (int n = 0; n < 8; n++) {
                const int o0 = (n * 8 + g) * 68 + kk * 8 + l;
                uint32_t bh0 = __float_as_uint(Kh[o0]);
                uint32_t bh1 = __float_as_uint(Kh[o0 + 4]);
                uint32_t bl0 = __float_as_uint(Kl[o0]);
                uint32_t bl1 = __float_as_uint(Kl[o0 + 4]);
                mma_tf32(sacc[n], qah[kk], bh0, bh1);
                mma_tf32(sacc[n], qal[kk], bh0, bh1);
                mma_tf32(sacc[n], qah[kk], bl0, bl1);
            }

        // Epilogue: +1, bias, causal mask, denom partials, stage fp32 S
        #pragma unroll
        for (int n = 0; n < 8; n++) {
            int jc = j0 + n * 8 + 2 * l;
            float v00, v01, v10, v11;
            if (full) {
                v00 = sacc[n][0] + 1.0f + qrv[n][0];
                v01 = sacc[n][1] + 1.0f + qrv[n][1];
                v10 = sacc[n][2] + 1.0f + qrv[n][2];
                v11 = sacc[n][3] + 1.0f + qrv[n][3];
            } else {
                v00 = (jc     <= i_lo) ? sacc[n][0] + 1.0f + qrv[n][0] : 0.0f;
                v01 = (jc + 1 <= i_lo) ? sacc[n][1] + 1.0f + qrv[n][1] : 0.0f;
                v10 = (jc     <= i_hi) ? sacc[n][2] + 1.0f + qrv[n][2] : 0.0f;
                v11 = (jc + 1 <= i_hi) ? sacc[n][3] + 1.0f + qrv[n][3] : 0.0f;
            }
            dp_lo += v00 + v01;
            dp_hi += v10 + v11;
            *reinterpret_cast<float2*>(Ss + r0 * 68 + n * 8 + 2 * l) =
                make_float2(v00, v01);
            *reinterpret_cast<float2*>(Ss + (r0 + 8) * 68 + n * 8 + 2 * l) =
                make_float2(v10, v11);
        }
        __syncwarp();

        // GEMM2: O += S . V  (3xTF32; A = S split on load, V pre-split)
        #pragma unroll
        for (int kk = 0; kk < 8; kk++) {
            uint32_t ah[4], al[4];
            split2(Ss[r0 * 68 + kk * 8 + l],           ah[0], al[0]);
            split2(Ss[(r0 + 8) * 68 + kk * 8 + l],     ah[1], al[1]);
            split2(Ss[r0 * 68 + kk * 8 + l + 4],       ah[2], al[2]);
            split2(Ss[(r0 + 8) * 68 + kk * 8 + l + 4], ah[3], al[3]);
            #pragma unroll
            for (int n = 0; n < 8; n++) {
                const int p0 = (kk * 8 + l) * 72 + n * 8 + g;
                const int p1 = (kk * 8 + l + 4) * 72 + n * 8 + g;
                uint32_t bh0 = __float_as_uint(Vh[p0]);
                uint32_t bh1 = __float_as_uint(Vh[p1]);
                uint32_t bl0 = __float_as_uint(Vl[p0]);
                uint32_t bl1 = __float_as_uint(Vl[p1]);
                mma_tf32(oacc[n], ah, bh0, bh1);
                mma_tf32(oacc[n], al, bh0, bh1);
                mma_tf32(oacc[n], ah, bl0, bl1);
            }
        }

        // next buffer ready + all warps done reading current buffers
        asm volatile("cp.async.wait_group 0;");
        __syncthreads();
    }

    // Row denominators: reduce across the 4 lanes of each quad
    dp_lo += __shfl_xor_sync(0xffffffffu, dp_lo, 1);
    dp_lo += __shfl_xor_sync(0xffffffffu, dp_lo, 2);
    dp_hi += __shfl_xor_sync(0xffffffffu, dp_hi, 1);
    dp_hi += __shfl_xor_sync(0xffffffffu, dp_hi, 2);
    const float rlo = 1.0f / dp_lo;
    const float rhi = 1.0f / dp_hi;

    float* olo = out + ((size_t)bh * N_ + i_lo) * D_;
    float* ohi = out + ((size_t)bh * N_ + i_hi) * D_;
    #pragma unroll
    for (int n = 0; n < 8; n++) {
        int dc = n * 8 + 2 * l;
        *reinterpret_cast<float2*>(olo + dc) =
            make_float2(oacc[n][0] * rlo, oacc[n][1] * rlo);
        *reinterpret_cast<float2*>(ohi + dc) =
            make_float2(oacc[n][2] * rhi, oacc[n][3] * rhi);
    }
}

// ---------------------------------------------------------------------------
extern "C" void kernel_launch(void* const* d_in, const int* in_sizes, int n_in,
                              void* d_out, int out_size) {
    const float* q   = (const float*)d_in[0];
    const float* k   = (const float*)d_in[1];
    const float* v   = (const float*)d_in[2];
    const float* dn  = (const float*)d_in[3];
    const float* rpe = (const float*)d_in[4];
    float* out = (float*)d_out;

    prep_norm_kernel<<<(2 * BH_ * N_) / 8, 256>>>(q, k);
    prep_v_kernel<<<(BH_ * N_ * D_ / 4) / 256, 256>>>(v, dn);

    const int qr_smem = (128 * 68 + 64 * 68) * sizeof(float);       // 52224 B
    cudaFuncSetAttribute(qr_mma_kernel,
                         cudaFuncAttributeMaxDynamicSharedMemorySize, qr_smem);
    qr_mma_kernel<<<dim3(16, 8, BH_), 256, qr_smem>>>(rpe);

    const int mn_smem = 44544 * sizeof(float);                      // 178176 B
    cudaFuncSetAttribute(fastmax_mma_kernel,
                         cudaFuncAttributeMaxDynamicSharedMemorySize, mn_smem);
    fastmax_mma_kernel<<<dim3(8, BH_), 256, mn_smem>>>(out);
}